// round 15
// baseline (speedup 1.0000x reference)
#include <cuda_runtime.h>
#include <cuda_bf16.h>
#include <cstdint>

typedef unsigned long long ull;

constexpr int Bn = 128;
constexpr int Tn = 1024;
constexpr int In = 256;
constexpr int Hn = 512;

// rnn smem layout (bytes)
constexpr int WS_BYTES  = 48 * 256 * 16;          // Wh smem: [48][256] float4 = 196608
constexpr int HP_PAIR   = 520;                    // padded ull per (buf,pair)
constexpr int HP_OFF    = WS_BYTES;
constexpr int HP_BYTES  = 2 * 2 * HP_PAIR * 8;    // 16640
constexpr int PART_OFF  = HP_OFF + HP_BYTES;      // partials: 256 slots x 16B
constexpr int PART_BYTES= 256 * 16;               // 4096
constexpr int MB_OFF    = PART_OFF + PART_BYTES;  // mbar[2][4]
constexpr int SMEM_RNN  = MB_OFF + 64;            // 217408

__device__ __forceinline__ ull pack2f(float x, float y) {
    ull r; asm("mov.b64 %0, {%1, %2};" : "=l"(r) : "f"(x), "f"(y)); return r;
}
__device__ __forceinline__ float2 unpack2f(ull v) {
    float2 r; asm("mov.b64 {%0, %1}, %2;" : "=f"(r.x), "=f"(r.y) : "l"(v)); return r;
}
__device__ __forceinline__ ull splat2f(float x) {
    ull r; asm("mov.b64 %0, {%1, %1};" : "=l"(r) : "f"(x)); return r;
}
__device__ __forceinline__ void ffma2(ull& a, ull x, ull y) {
    asm("fma.rn.f32x2 %0, %1, %2, %0;" : "+l"(a) : "l"(x), "l"(y));
}
__device__ __forceinline__ float sigmoidf_fast(float z) {
    return __fdividef(1.0f, 1.0f + __expf(-z));
}
__device__ __forceinline__ uint32_t smem_u32(const void* p) {
    return (uint32_t)__cvta_generic_to_shared(p);
}
__device__ __forceinline__ void mbar_wait(uint32_t maddr, uint32_t phase) {
    uint32_t done;
    do {
        asm volatile(
            "{\n\t.reg .pred p;\n\t"
            "mbarrier.try_wait.parity.acquire.cluster.shared::cta.b64 p, [%1], %2, 0x989680;\n\t"
            "selp.b32 %0, 1, 0, p;\n\t}"
            : "=r"(done) : "r"(maddr), "r"(phase) : "memory");
    } while (!done);
}

// ---------------------------------------------------------------------------
// Kernel 1: igates via bf16 tensor cores, 3-term split (round-13 winner).
// ---------------------------------------------------------------------------
constexpr int GI_BM = 128, GI_BN = 64, GI_BK = 32;
constexpr int GI_XS = GI_BK / 2 + 4;

__device__ __forceinline__ void mma_bf16(float* c, const unsigned* a, const unsigned* b) {
    asm volatile(
        "mma.sync.aligned.m16n8k16.row.col.f32.bf16.bf16.f32 "
        "{%0,%1,%2,%3}, {%4,%5,%6,%7}, {%8,%9}, {%0,%1,%2,%3};"
        : "+f"(c[0]), "+f"(c[1]), "+f"(c[2]), "+f"(c[3])
        : "r"(a[0]), "r"(a[1]), "r"(a[2]), "r"(a[3]), "r"(b[0]), "r"(b[1]));
}
__device__ __forceinline__ unsigned packbf(float f0, float f1) {
    __nv_bfloat162 t = __floats2bfloat162_rn(f0, f1);
    return reinterpret_cast<unsigned&>(t);
}

__global__ __launch_bounds__(256) void igates_tc_kernel(
    const float* __restrict__ X,
    const float* __restrict__ Wi,
    const float* __restrict__ bi,
    float* __restrict__ out)
{
    __shared__ unsigned Xh[GI_BM][GI_XS], Xl[GI_BM][GI_XS];
    __shared__ unsigned Wh[GI_BN][GI_XS], Wl[GI_BN][GI_XS];

    const int tid  = threadIdx.x;
    const int lane = tid & 31;
    const int warp = tid >> 5;
    const int wm   = warp & 3;
    const int wn   = warp >> 2;
    const int m0   = blockIdx.y * GI_BM;
    const int n0   = blockIdx.x * GI_BN;
    const int gr   = lane >> 2;
    const int gc   = lane & 3;

    float acc[2][4][4] = {};

    for (int k0 = 0; k0 < In; k0 += GI_BK) {
        #pragma unroll
        for (int i = 0; i < 4; i++) {
            int idx = tid + 256 * i;
            int r   = idx >> 3;
            int c4  = idx & 7;
            float4 v = *(const float4*)(X + (size_t)(m0 + r) * In + k0 + c4 * 4);
            float hx = __bfloat162float(__float2bfloat16(v.x));
            float hy = __bfloat162float(__float2bfloat16(v.y));
            float hz = __bfloat162float(__float2bfloat16(v.z));
            float hw = __bfloat162float(__float2bfloat16(v.w));
            Xh[r][c4*2]   = packbf(hx, hy);
            Xh[r][c4*2+1] = packbf(hz, hw);
            Xl[r][c4*2]   = packbf(v.x - hx, v.y - hy);
            Xl[r][c4*2+1] = packbf(v.z - hz, v.w - hw);
        }
        #pragma unroll
        for (int i = 0; i < 2; i++) {
            int idx = tid + 256 * i;
            int r   = idx >> 3;
            int c4  = idx & 7;
            float4 v = *(const float4*)(Wi + (size_t)(n0 + r) * In + k0 + c4 * 4);
            float hx = __bfloat162float(__float2bfloat16(v.x));
            float hy = __bfloat162float(__float2bfloat16(v.y));
            float hz = __bfloat162float(__float2bfloat16(v.z));
            float hw = __bfloat162float(__float2bfloat16(v.w));
            Wh[r][c4*2]   = packbf(hx, hy);
            Wh[r][c4*2+1] = packbf(hz, hw);
            Wl[r][c4*2]   = packbf(v.x - hx, v.y - hy);
            Wl[r][c4*2+1] = packbf(v.z - hz, v.w - hw);
        }
        __syncthreads();

        #pragma unroll
        for (int kb = 0; kb < 2; kb++) {
            const int c = kb * 8 + gc;
            unsigned ah[2][4], al[2][4];
            #pragma unroll
            for (int mt = 0; mt < 2; mt++) {
                int r = wm * 32 + mt * 16 + gr;
                ah[mt][0] = Xh[r][c];     ah[mt][1] = Xh[r+8][c];
                ah[mt][2] = Xh[r][c+4];   ah[mt][3] = Xh[r+8][c+4];
                al[mt][0] = Xl[r][c];     al[mt][1] = Xl[r+8][c];
                al[mt][2] = Xl[r][c+4];   al[mt][3] = Xl[r+8][c+4];
            }
            unsigned bh[4][2], bl[4][2];
            #pragma unroll
            for (int nt = 0; nt < 4; nt++) {
                int n = wn * 32 + nt * 8 + gr;
                bh[nt][0] = Wh[n][c];  bh[nt][1] = Wh[n][c+4];
                bl[nt][0] = Wl[n][c];  bl[nt][1] = Wl[n][c+4];
            }
            #pragma unroll
            for (int mt = 0; mt < 2; mt++)
                #pragma unroll
                for (int nt = 0; nt < 4; nt++) {
                    mma_bf16(acc[mt][nt], ah[mt], bh[nt]);
                    mma_bf16(acc[mt][nt], ah[mt], bl[nt]);
                    mma_bf16(acc[mt][nt], al[mt], bh[nt]);
                }
        }
        __syncthreads();
    }

    #pragma unroll
    for (int mt = 0; mt < 2; mt++) {
        int r = m0 + wm * 32 + mt * 16 + gr;
        #pragma unroll
        for (int nt = 0; nt < 4; nt++) {
            int cc = n0 + wn * 32 + nt * 8 + 2 * gc;
            float b0 = bi[cc], b1 = bi[cc + 1];
            float2 o0 = make_float2(acc[mt][nt][0] + b0, acc[mt][nt][1] + b1);
            float2 o1 = make_float2(acc[mt][nt][2] + b0, acc[mt][nt][3] + b1);
            *(float2*)(out + (size_t)r       * Hn + cc) = o0;
            *(float2*)(out + (size_t)(r + 8) * Hn + cc) = o1;
        }
    }
}

// ---------------------------------------------------------------------------
// Kernel 2: recurrence = R12 winner (per-source waits, aggregated arrives)
//   with the weight split changed 32reg/32smem -> 16reg/48smem to free ~64
//   registers for ptxas software pipelining of the LDS->FFMA chains.
//   Chunk c0 (k [0,128) of this thread's half) = regs u0..15 + smem su0..15;
//   chunk c1 (k [128,256)) = smem su16..47. Wait ordering preserved.
// ---------------------------------------------------------------------------
__global__ __launch_bounds__(256, 1) __cluster_dims__(4, 1, 1)
void rnn_kernel(
    float* __restrict__ out,
    const float* __restrict__ hidden,
    const float* __restrict__ Wh,
    const float* __restrict__ bh)
{
    extern __shared__ char sm[];
    float4* Wsm  = (float4*)sm;                  // [48][256]
    ull*    hpb  = (ull*)(sm + HP_OFF);          // [2 buf][2 pair][520]
    ull*    part = (ull*)(sm + PART_OFF);        // 256 slots x 2 ull
    ull*    mbar = (ull*)(sm + MB_OFF);          // [2 buf][4 src]

    const int tid  = threadIdx.x;
    const int lane = tid & 31;
    const int warp = tid >> 5;                   // 0..7
    const int p    = warp & 3;                   // column block
    const int rq   = warp >> 2;                  // k-half
    const int jj   = (p << 5) | lane;            // 0..127 column in slice
    uint32_t crank; asm("mov.u32 %0, %%cluster_ctarank;" : "=r"(crank));
    const int g    = blockIdx.x >> 2;
    const int j    = (int)crank * 128 + jj;      // global column
    const float bhj = bh[j];
    const int pr   = rq;                         // epilogue row-pair
    const int b0   = 4 * g + 2 * pr;
    const int jidx = j + ((j >> 8) << 3);        // padded column index

    float* __restrict__ hl = out + (size_t)Bn * Tn * Hn;

    // ---- Wh: k [256rq, 256rq+64) -> 16 f4 regs; k [256rq+64, 256rq+256) -> smem
    float4 W4[16];
    {
        const float4* wp = (const float4*)(Wh + (size_t)j * Hn + 256 * rq);
        #pragma unroll
        for (int u = 0; u < 16; u++) W4[u] = wp[u];
        const float4* wq = (const float4*)(Wh + (size_t)j * Hn + 256 * rq + 64);
        #pragma unroll
        for (int u = 0; u < 48; u++) Wsm[u * 256 + tid] = wq[u];
    }

    // ---- mbarrier init: 8 per-source barriers, count 1 each ----
    if (tid == 0) {
        #pragma unroll
        for (int m = 0; m < 8; m++) {
            asm volatile("mbarrier.init.shared.b64 [%0], %1;"
                         :: "r"(smem_u32(&mbar[m])), "r"(1u) : "memory");
        }
    }

    // ---- stage initial hidden into hp buf 0 ----
    for (int i = tid; i < 1024; i += 256) {
        int pair = i >> 9, col = i & 511;
        int idx  = col + ((col >> 8) << 3);
        hpb[pair * HP_PAIR + idx] =
            pack2f(hidden[(4 * g + 2 * pair) * Hn + col],
                   hidden[(4 * g + 2 * pair + 1) * Hn + col]);
    }
    __syncthreads();

    // cluster-wide: mbar init + staging complete before any remote store/arrive
    asm volatile("barrier.cluster.arrive.aligned;" ::: "memory");
    asm volatile("barrier.cluster.wait.aligned;"   ::: "memory");

    // ---- precompute remote addresses ----
    const uint32_t hp_u32 = smem_u32(hpb);
    const uint32_t mb_u32 = smem_u32(mbar);
    uint32_t rhp[4];
    #pragma unroll
    for (int r = 0; r < 4; r++) {
        asm("mapa.shared::cluster.u32 %0, %1, %2;" : "=r"(rhp[r]) : "r"(hp_u32), "r"(r));
    }
    // threads 0..3: remote address of rank-tid's mbar[buf][crank]
    uint32_t rmbA = 0, rmbB = 0;
    if (tid < 4) {
        asm("mapa.shared::cluster.u32 %0, %1, %2;"
            : "=r"(rmbA) : "r"(mb_u32 + (0u * 4u + crank) * 8u), "r"(tid));
        asm("mapa.shared::cluster.u32 %0, %1, %2;"
            : "=r"(rmbB) : "r"(mb_u32 + (1u * 4u + crank) * 8u), "r"(tid));
    }
    const uint32_t poff = (uint32_t)(pr * HP_PAIR + jidx) * 8u;
    const float4*  ws   = Wsm + tid;
    const int c0 = 2 * rq;                 // source of k [0,128) of this half
    const int c1 = 2 * rq + 1;             // source of k [128,256)
    const bool c1_local = ((int)crank == c1);

    const size_t orow0 = (size_t)b0       * (Tn * Hn);
    const size_t orow1 = (size_t)(b0 + 1) * (Tn * Hn);
    ull* mypart = part + (size_t)((p * 2 + rq) * 32 + lane) * 2;
    const ull* pppart = part + (size_t)((p * 2 + (rq ^ 1)) * 32 + lane) * 2;

    for (int t = 0; t < Tn; t++) {
        const int cur = t & 1;
        const int nb  = cur ^ 1;
        const uint32_t phase = (uint32_t)((t - 1) >> 1) & 1u;

        // igate prefetch (independent of h; overlaps waits + compute)
        const float ig0 = __ldcg(out + orow0 + (size_t)t * Hn + j);
        const float ig1 = __ldcg(out + orow1 + (size_t)t * Hn + j);

        const ull* hp0 = hpb + cur * (2 * HP_PAIR) + 0 * HP_PAIR + 264 * rq;
        const ull* hp1 = hpb + cur * (2 * HP_PAIR) + 1 * HP_PAIR + 264 * rq;
        ull a00 = 0, a01 = 0, a10 = 0, a11 = 0;

        // ---- chunk c1 first when local (no wait needed for own push) ----
        if (c1_local) {
            #pragma unroll
            for (int su = 16; su < 48; su++) {
                float4 w = ws[su * 256];
                ull wx = splat2f(w.x), wy = splat2f(w.y),
                    wz = splat2f(w.z), ww = splat2f(w.w);
                const int o = 64 + 4 * su;
                ulonglong2 h0a = *(const ulonglong2*)(hp0 + o);
                ulonglong2 h0b = *(const ulonglong2*)(hp0 + o + 2);
                ffma2(a00, wx, h0a.x); ffma2(a01, wy, h0a.y);
                ffma2(a00, wz, h0b.x); ffma2(a01, ww, h0b.y);
                ulonglong2 h1a = *(const ulonglong2*)(hp1 + o);
                ulonglong2 h1b = *(const ulonglong2*)(hp1 + o + 2);
                ffma2(a10, wx, h1a.x); ffma2(a11, wy, h1a.y);
                ffma2(a10, wz, h1b.x); ffma2(a11, ww, h1b.y);
            }
            if (t > 0) mbar_wait(mb_u32 + (uint32_t)(cur * 4 + c0) * 8u, phase);
        } else {
            if (t > 0 && c0 != (int)crank)
                mbar_wait(mb_u32 + (uint32_t)(cur * 4 + c0) * 8u, phase);
        }

        // ---- chunk c0: regs u0..15 (k 0..63) + smem su0..15 (k 64..127) ----
        #pragma unroll
        for (int u = 0; u < 16; u++) {
            float4 w = W4[u];
            ull wx = splat2f(w.x), wy = splat2f(w.y),
                wz = splat2f(w.z), ww = splat2f(w.w);
            ulonglong2 h0a = *(const ulonglong2*)(hp0 + 4*u);
            ulonglong2 h0b = *(const ulonglong2*)(hp0 + 4*u + 2);
            ffma2(a00, wx, h0a.x); ffma2(a01, wy, h0a.y);
            ffma2(a00, wz, h0b.x); ffma2(a01, ww, h0b.y);
            ulonglong2 h1a = *(const ulonglong2*)(hp1 + 4*u);
            ulonglong2 h1b = *(const ulonglong2*)(hp1 + 4*u + 2);
            ffma2(a10, wx, h1a.x); ffma2(a11, wy, h1a.y);
            ffma2(a10, wz, h1b.x); ffma2(a11, ww, h1b.y);
        }
        #pragma unroll
        for (int su = 0; su < 16; su++) {
            float4 w = ws[su * 256];
            ull wx = splat2f(w.x), wy = splat2f(w.y),
                wz = splat2f(w.z), ww = splat2f(w.w);
            const int o = 64 + 4 * su;
            ulonglong2 h0a = *(const ulonglong2*)(hp0 + o);
            ulonglong2 h0b = *(const ulonglong2*)(hp0 + o + 2);
            ffma2(a00, wx, h0a.x); ffma2(a01, wy, h0a.y);
            ffma2(a00, wz, h0b.x); ffma2(a01, ww, h0b.y);
            ulonglong2 h1a = *(const ulonglong2*)(hp1 + o);
            ulonglong2 h1b = *(const ulonglong2*)(hp1 + o + 2);
            ffma2(a10, wx, h1a.x); ffma2(a11, wy, h1a.y);
            ffma2(a10, wz, h1b.x); ffma2(a11, ww, h1b.y);
        }

        // ---- chunk c1 (smem su16..47) when not done first ----
        if (!c1_local) {
            if (t > 0) mbar_wait(mb_u32 + (uint32_t)(cur * 4 + c1) * 8u, phase);
            #pragma unroll
            for (int su = 16; su < 48; su++) {
                float4 w = ws[su * 256];
                ull wx = splat2f(w.x), wy = splat2f(w.y),
                    wz = splat2f(w.z), ww = splat2f(w.w);
                const int o = 64 + 4 * su;
                ulonglong2 h0a = *(const ulonglong2*)(hp0 + o);
                ulonglong2 h0b = *(const ulonglong2*)(hp0 + o + 2);
                ffma2(a00, wx, h0a.x); ffma2(a01, wy, h0a.y);
                ffma2(a00, wz, h0b.x); ffma2(a01, ww, h0b.y);
                ulonglong2 h1a = *(const ulonglong2*)(hp1 + o);
                ulonglong2 h1b = *(const ulonglong2*)(hp1 + o + 2);
                ffma2(a10, wx, h1a.x); ffma2(a11, wy, h1a.y);
                ffma2(a10, wz, h1b.x); ffma2(a11, ww, h1b.y);
            }
        }

        // combine even/odd chains -> this half's partials for both pairs
        float2 e0 = unpack2f(a00), o0 = unpack2f(a01);
        float2 e1 = unpack2f(a10), o1 = unpack2f(a11);
        const ull pk0 = pack2f(e0.x + o0.x, e0.y + o0.y);
        const ull pk1 = pack2f(e1.x + o1.x, e1.y + o1.y);

        // ---- k-half reduction via smem partials + named pair-barrier ----
        ((ulonglong2*)mypart)[0] = make_ulonglong2(pk0, pk1);
        asm volatile("bar.sync %0, %1;" :: "r"(p + 1), "r"(64) : "memory");
        const ull other = pppart[pr];
        const float2 mine  = unpack2f(pr ? pk1 : pk0);
        const float2 their = unpack2f(other);
        const float zx = mine.x + their.x + ig0 + bhj;
        const float zy = mine.y + their.y + ig1 + bhj;
        float h0v = sigmoidf_fast(zx);
        float h1v = sigmoidf_fast(zy);

        // ---- DSMEM push FIRST (critical path), to all 4 CTAs' hp[nb] ----
        const ull v = pack2f(h0v, h1v);
        const uint32_t boff = (uint32_t)(nb * 2 * HP_PAIR) * 8u + poff;
        #pragma unroll
        for (int r = 0; r < 4; r++) {
            asm volatile("st.shared::cluster.u64 [%0], %1;"
                         :: "r"(rhp[r] + boff), "l"(v) : "memory");
        }

        // ---- aggregated arrival: CTA-wide sync, then 4 parallel arrives ----
        __syncthreads();
        if (tid < 4) {
            const uint32_t rm = nb ? rmbB : rmbA;
            asm volatile("mbarrier.arrive.release.cluster.shared::cluster.b64 _, [%0];"
                         :: "r"(rm) : "memory");
        }

        // ---- global stores (off the inter-CTA critical path) ----
        out[orow0 + (size_t)t * Hn + j] = h0v;
        out[orow1 + (size_t)t * Hn + j] = h1v;
        if (t == Tn - 1) {
            hl[b0 * Hn + j]       = h0v;
            hl[(b0 + 1) * Hn + j] = h1v;
        }
    }

    // ---- REQUIRED: peers' DSMEM stores / arrivals may still target our SMEM
    asm volatile("barrier.cluster.arrive.aligned;" ::: "memory");
    asm volatile("barrier.cluster.wait.aligned;"   ::: "memory");
}

// ---------------------------------------------------------------------------
// Launch
// ---------------------------------------------------------------------------
extern "C" void kernel_launch(void* const* d_in, const int* in_sizes, int n_in,
                              void* d_out, int out_size)
{
    const float* x      = (const float*)d_in[0];   // [B, T, I]
    const float* hidden = (const float*)d_in[1];   // [B, H]
    const float* Wi     = (const float*)d_in[2];   // [H, I]
    const float* bi     = (const float*)d_in[3];   // [H]
    const float* Wh     = (const float*)d_in[4];   // [H, H]
    const float* bh     = (const float*)d_in[5];   // [H]
    float* out = (float*)d_out;                    // [B,T,H] then [B,H] h_last

    dim3 g1(Hn / GI_BN, (Bn * Tn) / GI_BM);
    igates_tc_kernel<<<g1, 256>>>(x, Wi, bi, out);

    static bool attr_set = false;
    if (!attr_set) {
        cudaFuncSetAttribute(rnn_kernel,
                             cudaFuncAttributeMaxDynamicSharedMemorySize, SMEM_RNN);
        attr_set = true;
    }
    rnn_kernel<<<128, 256, SMEM_RNN>>>(out, hidden, Wh, bh);
}

// round 16
// speedup vs baseline: 1.0966x; 1.0966x over previous
#include <cuda_runtime.h>
#include <cuda_bf16.h>
#include <cstdint>

typedef unsigned long long ull;

constexpr int Bn = 128;
constexpr int Tn = 1024;
constexpr int In = 256;
constexpr int Hn = 512;

// rnn smem layout (bytes) — exact R12 (3318us winner)
constexpr int WS_BYTES  = 32 * 256 * 16;          // Wh smem half: [32][256] float4 = 131072
constexpr int HP_PAIR   = 520;                    // padded ull per (buf,pair)
constexpr int HP_OFF    = WS_BYTES;
constexpr int HP_BYTES  = 2 * 2 * HP_PAIR * 8;    // 16640
constexpr int PART_OFF  = HP_OFF + HP_BYTES;      // partials: 256 slots x 16B
constexpr int PART_BYTES= 256 * 16;               // 4096
constexpr int MB_OFF    = PART_OFF + PART_BYTES;  // mbar[2][4]
constexpr int SMEM_RNN  = MB_OFF + 64;

__device__ __forceinline__ ull pack2f(float x, float y) {
    ull r; asm("mov.b64 %0, {%1, %2};" : "=l"(r) : "f"(x), "f"(y)); return r;
}
__device__ __forceinline__ float2 unpack2f(ull v) {
    float2 r; asm("mov.b64 {%0, %1}, %2;" : "=f"(r.x), "=f"(r.y) : "l"(v)); return r;
}
__device__ __forceinline__ ull splat2f(float x) {
    ull r; asm("mov.b64 %0, {%1, %1};" : "=l"(r) : "f"(x)); return r;
}
__device__ __forceinline__ void ffma2(ull& a, ull x, ull y) {
    asm("fma.rn.f32x2 %0, %1, %2, %0;" : "+l"(a) : "l"(x), "l"(y));
}
__device__ __forceinline__ float sigmoidf_fast(float z) {
    return __fdividef(1.0f, 1.0f + __expf(-z));
}
__device__ __forceinline__ uint32_t smem_u32(const void* p) {
    return (uint32_t)__cvta_generic_to_shared(p);
}
__device__ __forceinline__ void mbar_wait(uint32_t maddr, uint32_t phase) {
    uint32_t done;
    do {
        asm volatile(
            "{\n\t.reg .pred p;\n\t"
            "mbarrier.try_wait.parity.acquire.cluster.shared::cta.b64 p, [%1], %2, 0x989680;\n\t"
            "selp.b32 %0, 1, 0, p;\n\t}"
            : "=r"(done) : "r"(maddr), "r"(phase) : "memory");
    } while (!done);
}

// ---------------------------------------------------------------------------
// Kernel 1: igates via bf16 tensor cores, 3-term split. CTA tile 128m x 128n
//   (BN widened 64->128: X L2 re-reads halve, B-frag loads amortize 2x).
//   8 warps as 2m x 4n grid of 64x32 warp tiles, mma.sync.m16n8k16.
// ---------------------------------------------------------------------------
constexpr int GI_BM = 128, GI_BN = 128, GI_BK = 32;
constexpr int GI_XS = GI_BK / 2 + 4;              // 20-word row stride

__device__ __forceinline__ void mma_bf16(float* c, const unsigned* a, const unsigned* b) {
    asm volatile(
        "mma.sync.aligned.m16n8k16.row.col.f32.bf16.bf16.f32 "
        "{%0,%1,%2,%3}, {%4,%5,%6,%7}, {%8,%9}, {%0,%1,%2,%3};"
        : "+f"(c[0]), "+f"(c[1]), "+f"(c[2]), "+f"(c[3])
        : "r"(a[0]), "r"(a[1]), "r"(a[2]), "r"(a[3]), "r"(b[0]), "r"(b[1]));
}
__device__ __forceinline__ unsigned packbf(float f0, float f1) {
    __nv_bfloat162 t = __floats2bfloat162_rn(f0, f1);
    return reinterpret_cast<unsigned&>(t);
}

__global__ __launch_bounds__(256) void igates_tc_kernel(
    const float* __restrict__ X,
    const float* __restrict__ Wi,
    const float* __restrict__ bi,
    float* __restrict__ out)
{
    __shared__ unsigned Xh[GI_BM][GI_XS], Xl[GI_BM][GI_XS];
    __shared__ unsigned Wh[GI_BN][GI_XS], Wl[GI_BN][GI_XS];

    const int tid  = threadIdx.x;
    const int lane = tid & 31;
    const int warp = tid >> 5;
    const int wm   = warp & 1;        // 0..1: 64-row half
    const int wn   = warp >> 1;       // 0..3: 32-col block
    const int m0   = blockIdx.y * GI_BM;
    const int n0   = blockIdx.x * GI_BN;
    const int gr   = lane >> 2;       // 0..7
    const int gc   = lane & 3;        // 0..3

    float acc[4][4][4] = {};          // [m-tile][n-tile][frag]

    for (int k0 = 0; k0 < In; k0 += GI_BK) {
        // ---- stage X tile (128 x 32 floats): 4 float4 per thread ----
        #pragma unroll
        for (int i = 0; i < 4; i++) {
            int idx = tid + 256 * i;          // 0..1023
            int r   = idx >> 3;
            int c4  = idx & 7;
            float4 v = *(const float4*)(X + (size_t)(m0 + r) * In + k0 + c4 * 4);
            float hx = __bfloat162float(__float2bfloat16(v.x));
            float hy = __bfloat162float(__float2bfloat16(v.y));
            float hz = __bfloat162float(__float2bfloat16(v.z));
            float hw = __bfloat162float(__float2bfloat16(v.w));
            Xh[r][c4*2]   = packbf(hx, hy);
            Xh[r][c4*2+1] = packbf(hz, hw);
            Xl[r][c4*2]   = packbf(v.x - hx, v.y - hy);
            Xl[r][c4*2+1] = packbf(v.z - hz, v.w - hw);
        }
        // ---- stage W tile (128 x 32 floats): 4 float4 per thread ----
        #pragma unroll
        for (int i = 0; i < 4; i++) {
            int idx = tid + 256 * i;
            int r   = idx >> 3;
            int c4  = idx & 7;
            float4 v = *(const float4*)(Wi + (size_t)(n0 + r) * In + k0 + c4 * 4);
            float hx = __bfloat162float(__float2bfloat16(v.x));
            float hy = __bfloat162float(__float2bfloat16(v.y));
            float hz = __bfloat162float(__float2bfloat16(v.z));
            float hw = __bfloat162float(__float2bfloat16(v.w));
            Wh[r][c4*2]   = packbf(hx, hy);
            Wh[r][c4*2+1] = packbf(hz, hw);
            Wl[r][c4*2]   = packbf(v.x - hx, v.y - hy);
            Wl[r][c4*2+1] = packbf(v.z - hz, v.w - hw);
        }
        __syncthreads();

        #pragma unroll
        for (int kb = 0; kb < 2; kb++) {
            const int c = kb * 8 + gc;
            unsigned ah[4][4], al[4][4];
            #pragma unroll
            for (int mt = 0; mt < 4; mt++) {
                int r = wm * 64 + mt * 16 + gr;
                ah[mt][0] = Xh[r][c];     ah[mt][1] = Xh[r+8][c];
                ah[mt][2] = Xh[r][c+4];   ah[mt][3] = Xh[r+8][c+4];
                al[mt][0] = Xl[r][c];     al[mt][1] = Xl[r+8][c];
                al[mt][2] = Xl[r][c+4];   al[mt][3] = Xl[r+8][c+4];
            }
            unsigned bh[4][2], bl[4][2];
            #pragma unroll
            for (int nt = 0; nt < 4; nt++) {
                int n = wn * 32 + nt * 8 + gr;
                bh[nt][0] = Wh[n][c];  bh[nt][1] = Wh[n][c+4];
                bl[nt][0] = Wl[n][c];  bl[nt][1] = Wl[n][c+4];
            }
            #pragma unroll
            for (int mt = 0; mt < 4; mt++)
                #pragma unroll
                for (int nt = 0; nt < 4; nt++) {
                    mma_bf16(acc[mt][nt], ah[mt], bh[nt]);
                    mma_bf16(acc[mt][nt], ah[mt], bl[nt]);
                    mma_bf16(acc[mt][nt], al[mt], bh[nt]);
                }
        }
        __syncthreads();
    }

    // ---- epilogue: + bias, write f32 pairs ----
    #pragma unroll
    for (int mt = 0; mt < 4; mt++) {
        int r = m0 + wm * 64 + mt * 16 + gr;
        #pragma unroll
        for (int nt = 0; nt < 4; nt++) {
            int cc = n0 + wn * 32 + nt * 8 + 2 * gc;
            float b0 = bi[cc], b1 = bi[cc + 1];
            float2 o0 = make_float2(acc[mt][nt][0] + b0, acc[mt][nt][1] + b1);
            float2 o1 = make_float2(acc[mt][nt][2] + b0, acc[mt][nt][3] + b1);
            *(float2*)(out + (size_t)r       * Hn + cc) = o0;
            *(float2*)(out + (size_t)(r + 8) * Hn + cc) = o1;
        }
    }
}

// ---------------------------------------------------------------------------
// Kernel 2: recurrence — byte-identical to the R12 (3318us total) winner.
// ---------------------------------------------------------------------------
__device__ __forceinline__ void chunk_regs(
    const ull* __restrict__ hpP0, const ull* __restrict__ hpP1,
    const float4* __restrict__ W4,
    ull& a00, ull& a01, ull& a10, ull& a11)
{
    #pragma unroll
    for (int u = 0; u < 32; u++) {
        float4 w = W4[u];
        ull wx = splat2f(w.x), wy = splat2f(w.y),
            wz = splat2f(w.z), ww = splat2f(w.w);
        ulonglong2 h0a = *(const ulonglong2*)(hpP0 + 4*u);
        ulonglong2 h0b = *(const ulonglong2*)(hpP0 + 4*u + 2);
        ffma2(a00, wx, h0a.x); ffma2(a01, wy, h0a.y);
        ffma2(a00, wz, h0b.x); ffma2(a01, ww, h0b.y);
        ulonglong2 h1a = *(const ulonglong2*)(hpP1 + 4*u);
        ulonglong2 h1b = *(const ulonglong2*)(hpP1 + 4*u + 2);
        ffma2(a10, wx, h1a.x); ffma2(a11, wy, h1a.y);
        ffma2(a10, wz, h1b.x); ffma2(a11, ww, h1b.y);
    }
}
__device__ __forceinline__ void chunk_smem(
    const ull* __restrict__ hpP0, const ull* __restrict__ hpP1,
    const float4* __restrict__ ws,
    ull& a00, ull& a01, ull& a10, ull& a11)
{
    #pragma unroll
    for (int u = 0; u < 32; u++) {
        float4 w = ws[u * 256];
        ull wx = splat2f(w.x), wy = splat2f(w.y),
            wz = splat2f(w.z), ww = splat2f(w.w);
        ulonglong2 h0a = *(const ulonglong2*)(hpP0 + 4*u);
        ulonglong2 h0b = *(const ulonglong2*)(hpP0 + 4*u + 2);
        ffma2(a00, wx, h0a.x); ffma2(a01, wy, h0a.y);
        ffma2(a00, wz, h0b.x); ffma2(a01, ww, h0b.y);
        ulonglong2 h1a = *(const ulonglong2*)(hpP1 + 4*u);
        ulonglong2 h1b = *(const ulonglong2*)(hpP1 + 4*u + 2);
        ffma2(a10, wx, h1a.x); ffma2(a11, wy, h1a.y);
        ffma2(a10, wz, h1b.x); ffma2(a11, ww, h1b.y);
    }
}

__global__ __launch_bounds__(256, 1) __cluster_dims__(4, 1, 1)
void rnn_kernel(
    float* __restrict__ out,
    const float* __restrict__ hidden,
    const float* __restrict__ Wh,
    const float* __restrict__ bh)
{
    extern __shared__ char sm[];
    float4* Wsm  = (float4*)sm;                  // [32][256]
    ull*    hpb  = (ull*)(sm + HP_OFF);          // [2 buf][2 pair][520]
    ull*    part = (ull*)(sm + PART_OFF);        // 256 slots x 2 ull
    ull*    mbar = (ull*)(sm + MB_OFF);          // [2 buf][4 src]

    const int tid  = threadIdx.x;
    const int lane = tid & 31;
    const int warp = tid >> 5;                   // 0..7
    const int p    = warp & 3;                   // column block
    const int rq   = warp >> 2;                  // k-half
    const int jj   = (p << 5) | lane;            // 0..127 column in slice
    uint32_t crank; asm("mov.u32 %0, %%cluster_ctarank;" : "=r"(crank));
    const int g    = blockIdx.x >> 2;
    const int j    = (int)crank * 128 + jj;      // global column
    const float bhj = bh[j];
    const int pr   = rq;                         // epilogue row-pair
    const int b0   = 4 * g + 2 * pr;
    const int jidx = j + ((j >> 8) << 3);        // padded column index

    float* __restrict__ hl = out + (size_t)Bn * Tn * Hn;

    // ---- Wh: k [256rq,256rq+128) -> 128 regs; k [256rq+128,256rq+256) -> smem
    float4 W4[32];
    {
        const float4* wp = (const float4*)(Wh + (size_t)j * Hn + 256 * rq);
        #pragma unroll
        for (int u = 0; u < 32; u++) W4[u] = wp[u];
        const float4* wq = (const float4*)(Wh + (size_t)j * Hn + 256 * rq + 128);
        #pragma unroll
        for (int u = 0; u < 32; u++) Wsm[u * 256 + tid] = wq[u];
    }

    // ---- mbarrier init: 8 per-source barriers, count 1 each ----
    if (tid == 0) {
        #pragma unroll
        for (int m = 0; m < 8; m++) {
            asm volatile("mbarrier.init.shared.b64 [%0], %1;"
                         :: "r"(smem_u32(&mbar[m])), "r"(1u) : "memory");
        }
    }

    // ---- stage initial hidden into hp buf 0 ----
    for (int i = tid; i < 1024; i += 256) {
        int pair = i >> 9, col = i & 511;
        int idx  = col + ((col >> 8) << 3);
        hpb[pair * HP_PAIR + idx] =
            pack2f(hidden[(4 * g + 2 * pair) * Hn + col],
                   hidden[(4 * g + 2 * pair + 1) * Hn + col]);
    }
    __syncthreads();

    asm volatile("barrier.cluster.arrive.aligned;" ::: "memory");
    asm volatile("barrier.cluster.wait.aligned;"   ::: "memory");

    const uint32_t hp_u32 = smem_u32(hpb);
    const uint32_t mb_u32 = smem_u32(mbar);
    uint32_t rhp[4];
    #pragma unroll
    for (int r = 0; r < 4; r++) {
        asm("mapa.shared::cluster.u32 %0, %1, %2;" : "=r"(rhp[r]) : "r"(hp_u32), "r"(r));
    }
    uint32_t rmbA = 0, rmbB = 0;
    if (tid < 4) {
        asm("mapa.shared::cluster.u32 %0, %1, %2;"
            : "=r"(rmbA) : "r"(mb_u32 + (0u * 4u + crank) * 8u), "r"(tid));
        asm("mapa.shared::cluster.u32 %0, %1, %2;"
            : "=r"(rmbB) : "r"(mb_u32 + (1u * 4u + crank) * 8u), "r"(tid));
    }
    const uint32_t poff = (uint32_t)(pr * HP_PAIR + jidx) * 8u;
    const float4*  ws   = Wsm + tid;
    const int c0 = 2 * rq;
    const int c1 = 2 * rq + 1;
    const bool smem_first = ((int)crank == c1);

    const size_t orow0 = (size_t)b0       * (Tn * Hn);
    const size_t orow1 = (size_t)(b0 + 1) * (Tn * Hn);
    ull* mypart = part + (size_t)((p * 2 + rq) * 32 + lane) * 2;
    const ull* pppart = part + (size_t)((p * 2 + (rq ^ 1)) * 32 + lane) * 2;

    for (int t = 0; t < Tn; t++) {
        const int cur = t & 1;
        const int nb  = cur ^ 1;
        const uint32_t phase = (uint32_t)((t - 1) >> 1) & 1u;

        const float ig0 = __ldcg(out + orow0 + (size_t)t * Hn + j);
        const float ig1 = __ldcg(out + orow1 + (size_t)t * Hn + j);

        const ull* bP0 = hpb + cur * (2 * HP_PAIR) + 0 * HP_PAIR + 264 * rq;
        const ull* bP1 = hpb + cur * (2 * HP_PAIR) + 1 * HP_PAIR + 264 * rq;
        ull a00 = 0, a01 = 0, a10 = 0, a11 = 0;

        if (smem_first) {
            chunk_smem(bP0 + 128, bP1 + 128, ws, a00, a01, a10, a11);
            if (t > 0) mbar_wait(mb_u32 + (uint32_t)(cur * 4 + c0) * 8u, phase);
            chunk_regs(bP0, bP1, W4, a00, a01, a10, a11);
        } else {
            if (t > 0 && c0 != (int)crank)
                mbar_wait(mb_u32 + (uint32_t)(cur * 4 + c0) * 8u, phase);
            chunk_regs(bP0, bP1, W4, a00, a01, a10, a11);
            if (t > 0 && c1 != (int)crank)
                mbar_wait(mb_u32 + (uint32_t)(cur * 4 + c1) * 8u, phase);
            chunk_smem(bP0 + 128, bP1 + 128, ws, a00, a01, a10, a11);
        }

        float2 e0 = unpack2f(a00), o0 = unpack2f(a01);
        float2 e1 = unpack2f(a10), o1 = unpack2f(a11);
        const ull pk0 = pack2f(e0.x + o0.x, e0.y + o0.y);
        const ull pk1 = pack2f(e1.x + o1.x, e1.y + o1.y);

        ((ulonglong2*)mypart)[0] = make_ulonglong2(pk0, pk1);
        asm volatile("bar.sync %0, %1;" :: "r"(p + 1), "r"(64) : "memory");
        const ull other = pppart[pr];
        const float2 mine  = unpack2f(pr ? pk1 : pk0);
        const float2 their = unpack2f(other);
        const float zx = mine.x + their.x + ig0 + bhj;
        const float zy = mine.y + their.y + ig1 + bhj;
        float h0v = sigmoidf_fast(zx);
        float h1v = sigmoidf_fast(zy);

        const ull v = pack2f(h0v, h1v);
        const uint32_t boff = (uint32_t)(nb * 2 * HP_PAIR) * 8u + poff;
        #pragma unroll
        for (int r = 0; r < 4; r++) {
            asm volatile("st.shared::cluster.u64 [%0], %1;"
                         :: "r"(rhp[r] + boff), "l"(v) : "memory");
        }

        __syncthreads();
        if (tid < 4) {
            const uint32_t rm = nb ? rmbB : rmbA;
            asm volatile("mbarrier.arrive.release.cluster.shared::cluster.b64 _, [%0];"
                         :: "r"(rm) : "memory");
        }

        out[orow0 + (size_t)t * Hn + j] = h0v;
        out[orow1 + (size_t)t * Hn + j] = h1v;
        if (t == Tn - 1) {
            hl[b0 * Hn + j]       = h0v;
            hl[(b0 + 1) * Hn + j] = h1v;
        }
    }

    asm volatile("barrier.cluster.arrive.aligned;" ::: "memory");
    asm volatile("barrier.cluster.wait.aligned;"   ::: "memory");
}

// ---------------------------------------------------------------------------
// Launch
// ---------------------------------------------------------------------------
extern "C" void kernel_launch(void* const* d_in, const int* in_sizes, int n_in,
                              void* d_out, int out_size)
{
    const float* x      = (const float*)d_in[0];   // [B, T, I]
    const float* hidden = (const float*)d_in[1];   // [B, H]
    const float* Wi     = (const float*)d_in[2];   // [H, I]
    const float* bi     = (const float*)d_in[3];   // [H]
    const float* Wh     = (const float*)d_in[4];   // [H, H]
    const float* bh     = (const float*)d_in[5];   // [H]
    float* out = (float*)d_out;                    // [B,T,H] then [B,H] h_last

    dim3 g1(Hn / GI_BN, (Bn * Tn) / GI_BM);        // (4, 1024)
    igates_tc_kernel<<<g1, 256>>>(x, Wi, bi, out);

    static bool attr_set = false;
    if (!attr_set) {
        cudaFuncSetAttribute(rnn_kernel,
                             cudaFuncAttributeMaxDynamicSharedMemorySize, SMEM_RNN);
        attr_set = true;
    }
    rnn_kernel<<<128, 256, SMEM_RNN>>>(out, hidden, Wh, bh);
}